// round 14
// baseline (speedup 1.0000x reference)
#include <cuda_runtime.h>
#include <cuda_fp16.h>
#include <math_constants.h>
#include <cstdint>

#define NN 100000
#define EMAX 1700000
#define SCAN_BS 1024
#define NB ((NN + SCAN_BS - 1) / SCAN_BS)   // 98

// ---------------- device scratch (static globals; no allocation) -------------
__device__ __align__(16) __half g_y [NN * 64];  // (XW)*ns fp16, gather source
__device__ __align__(16) __half g_h1[NN * 64];  // layer-1 output (fp16)
__device__ __align__(16) __half g_h2[NN * 64];  // layer-2 output (fp16)
__device__ float g_ns[NN];
__device__ float g_nd[NN];
__device__ int g_cnt_out[NN];                   // zeroed by scan kernel of PREVIOUS call
__device__ int g_cnt_in [NN];
__device__ int g_cursor [NN];
__device__ int g_rowptr [NN + 1];
__device__ int2 g_edge[EMAX];                   // packed (src,dst) from hist
__device__ int g_esrc[EMAX];                    // src indices sorted by dst
__device__ unsigned g_epoch = 0;                // bumped once per call
__device__ unsigned long long g_bsflag[NB];     // (epoch<<32)|block_aggregate

__device__ __forceinline__ int load_idx(const void* p, int i, int is64) {
    return is64 ? (int)((const long long*)p)[i] : ((const int*)p)[i];
}

// ---------------- tensor-core GEMM body: Y = (X @ W) [*ns], fp16 out ----------
__device__ __forceinline__ void mma16816(
        float& c0, float& c1, float& c2, float& c3,
        uint32_t a0, uint32_t a1, uint32_t a2, uint32_t a3,
        uint32_t b0, uint32_t b1) {
    asm volatile(
        "mma.sync.aligned.m16n8k16.row.col.f32.f16.f16.f32 "
        "{%0,%1,%2,%3}, {%4,%5,%6,%7}, {%8,%9}, {%0,%1,%2,%3};"
        : "+f"(c0), "+f"(c1), "+f"(c2), "+f"(c3)
        : "r"(a0), "r"(a1), "r"(a2), "r"(a3), "r"(b0), "r"(b1));
}

template<int IN, int OUT, bool XF32, bool SCALE>
__device__ __forceinline__ void gemm_body(
        const void* __restrict__ Xv, const float* __restrict__ W,
        __half2* __restrict__ Yh, int row0, __half* sh) {
    constexpr int SX = IN + 8;              // half stride
    __half* Xs = sh;                        // 128 * SX
    __half* Bs = sh + 128 * SX;             // OUT * SX  (Bs[n][k] = W[k][n])
    int tid = threadIdx.x;

    for (int i = tid; i < IN * OUT; i += 256) {
        int k = i / OUT, n = i % OUT;
        Bs[n * SX + k] = __float2half_rn(W[i]);
    }
    if (XF32) {
        const float* X = (const float*)Xv;
        for (int i = tid; i < 128 * (IN / 4); i += 256) {
            int r = i / (IN / 4), c = i % (IN / 4);
            int gr = row0 + r;
            float4 v = (gr < NN) ? __ldg((const float4*)&X[(size_t)gr * IN + c * 4])
                                 : make_float4(0.f, 0.f, 0.f, 0.f);
            *(__half2*)&Xs[r * SX + c * 4]     = __floats2half2_rn(v.x, v.y);
            *(__half2*)&Xs[r * SX + c * 4 + 2] = __floats2half2_rn(v.z, v.w);
        }
    } else {
        const __half* X = (const __half*)Xv;
        for (int i = tid; i < 128 * (IN / 8); i += 256) {
            int r = i / (IN / 8), c = i % (IN / 8);
            int gr = row0 + r;
            uint4 v = (gr < NN) ? *(const uint4*)&X[(size_t)gr * IN + c * 8]
                                : make_uint4(0u, 0u, 0u, 0u);
            *(uint4*)&Xs[r * SX + c * 8] = v;
        }
    }
    __syncthreads();

    int warp = tid >> 5, lane = tid & 31;
    int g = lane >> 2, t = lane & 3;
    int m0 = warp * 16;
    constexpr int NT = OUT / 8;
    float acc[NT][4];
    #pragma unroll
    for (int nt = 0; nt < NT; nt++) {
        acc[nt][0] = 0.f; acc[nt][1] = 0.f; acc[nt][2] = 0.f; acc[nt][3] = 0.f;
    }

    #pragma unroll
    for (int k0 = 0; k0 < IN; k0 += 16) {
        const __half* ar0 = &Xs[(m0 + g) * SX + k0];
        const __half* ar8 = ar0 + 8 * SX;
        uint32_t a0 = *(const uint32_t*)&ar0[2 * t];
        uint32_t a1 = *(const uint32_t*)&ar8[2 * t];
        uint32_t a2 = *(const uint32_t*)&ar0[2 * t + 8];
        uint32_t a3 = *(const uint32_t*)&ar8[2 * t + 8];
        #pragma unroll
        for (int nt = 0; nt < NT; nt++) {
            const __half* br = &Bs[(nt * 8 + g) * SX + k0];
            uint32_t b0 = *(const uint32_t*)&br[2 * t];
            uint32_t b1 = *(const uint32_t*)&br[2 * t + 8];
            mma16816(acc[nt][0], acc[nt][1], acc[nt][2], acc[nt][3],
                     a0, a1, a2, a3, b0, b1);
        }
    }

    int r0 = row0 + m0 + g, r1 = r0 + 8;
    float s0 = 1.f, s1 = 1.f;
    if (SCALE) {
        if (r0 < NN) s0 = g_ns[r0];
        if (r1 < NN) s1 = g_ns[r1];
    }
    constexpr int STR = OUT / 2;
    #pragma unroll
    for (int nt = 0; nt < NT; nt++) {
        int cp = nt * 4 + t;
        if (r0 < NN)
            Yh[(size_t)r0 * STR + cp] = __floats2half2_rn(acc[nt][0] * s0,
                                                          acc[nt][1] * s0);
        if (r1 < NN)
            Yh[(size_t)r1 * STR + cp] = __floats2half2_rn(acc[nt][2] * s1,
                                                          acc[nt][3] * s1);
    }
}

// ---------------- fused: edge histogram + pack || layer-0 GEMM ----------------
__global__ void __launch_bounds__(256) histgemm0_kernel(
        const void* __restrict__ src, const void* __restrict__ dst, int E,
        int EB, const float* __restrict__ X, const float* __restrict__ W0,
        __half2* __restrict__ Yh) {
    extern __shared__ __half sh[];
    if ((int)blockIdx.x < EB) {
        __shared__ int s_is64;
        if (threadIdx.x == 0) {
            if (blockIdx.x == 0) g_epoch = g_epoch + 1;
            const long long* p = (const long long*)src;
            int n = E < 8 ? E : 8;
            int ok = 1;
            for (int j = 0; j < n; j++) {
                long long v = p[j];
                if (v < 0 || v >= (long long)NN) { ok = 0; break; }
            }
            s_is64 = ok;
        }
        __syncthreads();
        int is64 = s_is64;
        int e = blockIdx.x * 256 + threadIdx.x;
        if (e < E) {
            int s = load_idx(src, e, is64);
            int d = load_idx(dst, e, is64);
            atomicAdd(&g_cnt_out[s], 1);
            atomicAdd(&g_cnt_in [d], 1);
            g_edge[e] = make_int2(s, d);
        }
        return;
    }
    gemm_body<128, 64, true, false>(X, W0, Yh, (blockIdx.x - EB) * 128, sh);
}

// ---------------- standalone GEMM (layers 1, 2) -------------------------------
template<int IN, int OUT>
__global__ void __launch_bounds__(256) gemm_mma_kernel(
        const __half* __restrict__ X, const float* __restrict__ W,
        __half2* __restrict__ Yh) {
    extern __shared__ __half sh[];
    gemm_body<IN, OUT, false, true>(X, W, Yh, blockIdx.x * 128, sh);
}

// ---------------- single-launch chained scan + finalize -----------------------
__global__ void __launch_bounds__(SCAN_BS) scan_kernel(__half2* __restrict__ Yh) {
    __shared__ int sh[SCAN_BS];
    __shared__ int s_carry;
    unsigned ep = g_epoch;
    int tid = threadIdx.x, b = blockIdx.x;
    int i = b * SCAN_BS + tid;
    int v = (i < NN) ? g_cnt_in[i] : 0;
    sh[tid] = v;
    __syncthreads();
    #pragma unroll
    for (int off = 1; off < SCAN_BS; off <<= 1) {
        int t = (tid >= off) ? sh[tid - off] : 0;
        __syncthreads();
        sh[tid] += t;
        __syncthreads();
    }
    if (tid == SCAN_BS - 1)
        *(volatile unsigned long long*)&g_bsflag[b] =
            ((unsigned long long)ep << 32) | (unsigned)sh[SCAN_BS - 1];
    if (tid == 0) s_carry = 0;
    __syncthreads();
    if (tid < b) {
        volatile unsigned long long* f = &g_bsflag[tid];
        unsigned long long w;
        do { w = *f; } while ((unsigned)(w >> 32) != ep);
        atomicAdd(&s_carry, (int)(unsigned)w);
    }
    __syncthreads();
    int carry = s_carry;

    if (i < NN) {
        g_rowptr[i] = carry + sh[tid] - v;      // exclusive prefix
        int o = g_cnt_out[i];
        g_cnt_out[i] = 0;                        // pre-zero for NEXT call
        g_cnt_in [i] = 0;
        g_cursor [i] = 0;
        float nsv = (o > 0) ? rsqrtf((float)o) : 0.f;
        g_ns[i] = nsv;
        g_nd[i] = (v > 0) ? rsqrtf((float)v) : 0.f;
        __half2 h2s = __floats2half2_rn(nsv, nsv);
        __half2* yr = &Yh[(size_t)i * 32];
        #pragma unroll
        for (int j = 0; j < 32; j++)
            yr[j] = __hmul2(yr[j], h2s);
    }
    if (b == NB - 1 && tid == SCAN_BS - 1)
        g_rowptr[NN] = carry + sh[tid];          // == E
}

// ---------------- edge placement: CSR by dst (packed edges) -------------------
__global__ void place_kernel(int E) {
    int e = blockIdx.x * blockDim.x + threadIdx.x;
    if (e >= E) return;
    int2 sd = g_edge[e];
    int pos = g_rowptr[sd.y] + atomicAdd(&g_cursor[sd.y], 1);
    g_esrc[pos] = sd.x;
}

// ---------------- fused SpMM-gather (fp16) + epilogue -------------------------
// 4 rows per warp: 8-lane group per row, lane covers 8 cols (uint4 = LDG.128).
// Warp advances all 4 rows in lockstep over max length; per-group predication;
// width-8 shuffles broadcast edge indices. Epilogue amortized over 4 rows.
template<int OUT, bool RELU, bool O16>
__global__ void __launch_bounds__(256) spmm_epi_kernel(
        const __half2* __restrict__ Yh, const float* __restrict__ bias,
        void* __restrict__ OutV) {
    constexpr int STR4 = OUT / 8;            // uint4 per row
    int lane = threadIdx.x & 31;
    int g = lane >> 3, l8 = lane & 7;
    int warp = threadIdx.x >> 5;
    int row = blockIdx.x * 32 + warp * 4 + g;   // NN = 32 * 3125 exactly
    bool cvalid = l8 < STR4;
    const uint4* Yp = (const uint4*)Yh;

    int beg = g_rowptr[row];
    int len = g_rowptr[row + 1] - beg;
    int lm = len;
    lm = max(lm, __shfl_xor_sync(0xffffffffu, lm, 8));
    lm = max(lm, __shfl_xor_sync(0xffffffffu, lm, 16));

    float a[8] = {};
    for (int base = 0; base < lm; base += 8) {
        int rem = len - base;  if (rem > 8) rem = 8;       // per-group
        int remmax = lm - base; if (remmax > 8) remmax = 8; // warp-uniform
        int my = (l8 < rem) ? g_esrc[beg + base + l8] : 0;
        #pragma unroll 2
        for (int j = 0; j < remmax; j++) {
            int s = __shfl_sync(0xffffffffu, my, j, 8);
            if (cvalid && j < rem) {
                uint4 r = __ldg(&Yp[s * STR4 + l8]);
                float2 f0 = __half22float2(*(__half2*)&r.x);
                float2 f1 = __half22float2(*(__half2*)&r.y);
                float2 f2 = __half22float2(*(__half2*)&r.z);
                float2 f3 = __half22float2(*(__half2*)&r.w);
                a[0] += f0.x; a[1] += f0.y; a[2] += f1.x; a[3] += f1.y;
                a[4] += f2.x; a[5] += f2.y; a[6] += f3.x; a[7] += f3.y;
            }
        }
    }

    float ndv = g_nd[row];
    int c0 = 8 * l8;
    float v[8];
    float m = -CUDART_INF_F;
    if (cvalid) {
        float4 ba = __ldg((const float4*)&bias[c0]);
        float4 bb = __ldg((const float4*)&bias[c0 + 4]);
        v[0] = a[0] * ndv + ba.x; v[1] = a[1] * ndv + ba.y;
        v[2] = a[2] * ndv + ba.z; v[3] = a[3] * ndv + ba.w;
        v[4] = a[4] * ndv + bb.x; v[5] = a[5] * ndv + bb.y;
        v[6] = a[6] * ndv + bb.z; v[7] = a[7] * ndv + bb.w;
        #pragma unroll
        for (int i = 0; i < 8; i++) {
            if (RELU) v[i] = fmaxf(v[i], 0.f);
            m = fmaxf(m, v[i]);
        }
    }
    // reduce within each 8-lane group (offsets 4,2,1 stay in-group)
    #pragma unroll
    for (int o = 4; o; o >>= 1) m = fmaxf(m, __shfl_xor_sync(0xffffffffu, m, o));
    float s = 0.f;
    if (cvalid) {
        #pragma unroll
        for (int i = 0; i < 8; i++) s += __expf(v[i] - m);
    }
    #pragma unroll
    for (int o = 4; o; o >>= 1) s += __shfl_xor_sync(0xffffffffu, s, o);
    float ls = logf(s) + m;

    if (cvalid) {
        if (O16) {
            __half2 h0 = __floats2half2_rn(v[0] - ls, v[1] - ls);
            __half2 h1 = __floats2half2_rn(v[2] - ls, v[3] - ls);
            __half2 h2 = __floats2half2_rn(v[4] - ls, v[5] - ls);
            __half2 h3 = __floats2half2_rn(v[6] - ls, v[7] - ls);
            uint4 w;
            w.x = *(uint32_t*)&h0; w.y = *(uint32_t*)&h1;
            w.z = *(uint32_t*)&h2; w.w = *(uint32_t*)&h3;
            ((uint4*)OutV)[(size_t)row * STR4 + l8] = w;
        } else {
            float* Out = (float*)OutV;
            *(float4*)&Out[(size_t)row * OUT + c0] =
                make_float4(v[0] - ls, v[1] - ls, v[2] - ls, v[3] - ls);
            *(float4*)&Out[(size_t)row * OUT + c0 + 4] =
                make_float4(v[4] - ls, v[5] - ls, v[6] - ls, v[7] - ls);
        }
    }
}

// ---------------- launcher ----------------------------------------------------
extern "C" void kernel_launch(void* const* d_in, const int* in_sizes, int n_in,
                              void* d_out, int out_size) {
    const float* feats = (const float*)d_in[0];
    const void*  src   = d_in[1];
    const void*  dst   = d_in[2];
    const float* W0    = (const float*)d_in[3];
    const float* b0    = (const float*)d_in[4];
    const float* W1    = (const float*)d_in[5];
    const float* b1    = (const float*)d_in[6];
    const float* W2    = (const float*)d_in[7];
    const float* b2    = (const float*)d_in[8];
    float* out = (float*)d_out;
    int E = in_sizes[1];

    __half2* p_y = nullptr;
    __half *p_h1 = nullptr, *p_h2 = nullptr;
    cudaGetSymbolAddress((void**)&p_y,  g_y);
    cudaGetSymbolAddress((void**)&p_h1, g_h1);
    cudaGetSymbolAddress((void**)&p_h2, g_h2);

    const int MB = (NN + 127) / 128;  // gemm blocks (128 rows each)
    const int SB = NN / 32;           // spmm blocks (4 rows/warp, 8 warps) = 3125
    const int EB = (E + 255) / 256;   // per-edge blocks

    const int sm0 = (128 * (128 + 8) + 64 * (128 + 8)) * 2;  // 52224
    const int sm1 = (128 * (64 + 8) + 64 * (64 + 8)) * 2;    // 27648
    const int sm2 = (128 * (64 + 8) + 40 * (64 + 8)) * 2;    // 24192
    cudaFuncSetAttribute(histgemm0_kernel,
                         cudaFuncAttributeMaxDynamicSharedMemorySize, sm0);

    // 1) hist+pack || GEMM0 (one launch)
    histgemm0_kernel<<<EB + MB, 256, sm0>>>(src, dst, E, EB, feats, W0, p_y);
    // 2) chained scan + finalize (+Y0*=ns, zero cnts for next call)
    scan_kernel<<<NB, SCAN_BS>>>(p_y);
    // 3) CSR placement
    place_kernel<<<EB, 256>>>(E);
    // 4) layer 0 spmm+epilogue -> h1 (fp16)
    spmm_epi_kernel<64, true, true><<<SB, 256>>>(p_y, b0, p_h1);
    // 5) layer 1
    gemm_mma_kernel<64, 64><<<MB, 256, sm1>>>(p_h1, W1, p_y);
    spmm_epi_kernel<64, true, true><<<SB, 256>>>(p_y, b1, p_h2);
    // 6) layer 2
    gemm_mma_kernel<64, 40><<<MB, 256, sm2>>>(p_h2, W2, p_y);
    spmm_epi_kernel<40, false, false><<<SB, 256>>>(p_y, b2, out);
}

// round 15
// speedup vs baseline: 1.4876x; 1.4876x over previous
#include <cuda_runtime.h>
#include <cuda_fp16.h>
#include <math_constants.h>
#include <cstdint>

#define NN 100000
#define EMAX 1700000
#define SCAN_BS 1024
#define NB ((NN + SCAN_BS - 1) / SCAN_BS)   // 98

// ---------------- device scratch (static globals; no allocation) -------------
// All Y rows are 64 halves (128 bytes) regardless of logical OUT.
__device__ __align__(16) __half g_y [NN * 64];  // (XW)*ns fp16, gather source
__device__ __align__(16) __half g_h1[NN * 64];  // layer-1 output (fp16)
__device__ __align__(16) __half g_h2[NN * 64];  // layer-2 output (fp16)
__device__ float g_ns[NN];
__device__ float g_nd[NN];
__device__ int g_cnt_out[NN];                   // zeroed by scan kernel of PREVIOUS call
__device__ int g_cnt_in [NN];
__device__ int g_cursor [NN];
__device__ int g_rowptr [NN + 1];
__device__ int2 g_edge[EMAX];                   // packed (src,dst) from hist
__device__ int g_esrc[EMAX];                    // BYTE offsets (src*128), sorted by dst
__device__ unsigned g_epoch = 0;                // bumped once per call
__device__ unsigned long long g_bsflag[NB];     // (epoch<<32)|block_aggregate

__device__ __forceinline__ int load_idx(const void* p, int i, int is64) {
    return is64 ? (int)((const long long*)p)[i] : ((const int*)p)[i];
}

// ---------------- tensor-core GEMM body: Y = (X @ W) [*ns], fp16 out ----------
__device__ __forceinline__ void mma16816(
        float& c0, float& c1, float& c2, float& c3,
        uint32_t a0, uint32_t a1, uint32_t a2, uint32_t a3,
        uint32_t b0, uint32_t b1) {
    asm volatile(
        "mma.sync.aligned.m16n8k16.row.col.f32.f16.f16.f32 "
        "{%0,%1,%2,%3}, {%4,%5,%6,%7}, {%8,%9}, {%0,%1,%2,%3};"
        : "+f"(c0), "+f"(c1), "+f"(c2), "+f"(c3)
        : "r"(a0), "r"(a1), "r"(a2), "r"(a3), "r"(b0), "r"(b1));
}

// YSTR = output row stride in half2 units (32 for the padded 128B rows)
template<int IN, int OUT, int YSTR, bool XF32, bool SCALE>
__device__ __forceinline__ void gemm_body(
        const void* __restrict__ Xv, const float* __restrict__ W,
        __half2* __restrict__ Yh, int row0, __half* sh) {
    constexpr int SX = IN + 8;              // half stride
    __half* Xs = sh;                        // 128 * SX
    __half* Bs = sh + 128 * SX;             // OUT * SX  (Bs[n][k] = W[k][n])
    int tid = threadIdx.x;

    for (int i = tid; i < IN * OUT; i += 256) {
        int k = i / OUT, n = i % OUT;
        Bs[n * SX + k] = __float2half_rn(W[i]);
    }
    if (XF32) {
        const float* X = (const float*)Xv;
        for (int i = tid; i < 128 * (IN / 4); i += 256) {
            int r = i / (IN / 4), c = i % (IN / 4);
            int gr = row0 + r;
            float4 v = (gr < NN) ? __ldg((const float4*)&X[(size_t)gr * IN + c * 4])
                                 : make_float4(0.f, 0.f, 0.f, 0.f);
            *(__half2*)&Xs[r * SX + c * 4]     = __floats2half2_rn(v.x, v.y);
            *(__half2*)&Xs[r * SX + c * 4 + 2] = __floats2half2_rn(v.z, v.w);
        }
    } else {
        const __half* X = (const __half*)Xv;
        for (int i = tid; i < 128 * (IN / 8); i += 256) {
            int r = i / (IN / 8), c = i % (IN / 8);
            int gr = row0 + r;
            uint4 v = (gr < NN) ? *(const uint4*)&X[(size_t)gr * IN + c * 8]
                                : make_uint4(0u, 0u, 0u, 0u);
            *(uint4*)&Xs[r * SX + c * 8] = v;
        }
    }
    __syncthreads();

    int warp = tid >> 5, lane = tid & 31;
    int g = lane >> 2, t = lane & 3;
    int m0 = warp * 16;
    constexpr int NT = OUT / 8;
    float acc[NT][4];
    #pragma unroll
    for (int nt = 0; nt < NT; nt++) {
        acc[nt][0] = 0.f; acc[nt][1] = 0.f; acc[nt][2] = 0.f; acc[nt][3] = 0.f;
    }

    #pragma unroll
    for (int k0 = 0; k0 < IN; k0 += 16) {
        const __half* ar0 = &Xs[(m0 + g) * SX + k0];
        const __half* ar8 = ar0 + 8 * SX;
        uint32_t a0 = *(const uint32_t*)&ar0[2 * t];
        uint32_t a1 = *(const uint32_t*)&ar8[2 * t];
        uint32_t a2 = *(const uint32_t*)&ar0[2 * t + 8];
        uint32_t a3 = *(const uint32_t*)&ar8[2 * t + 8];
        #pragma unroll
        for (int nt = 0; nt < NT; nt++) {
            const __half* br = &Bs[(nt * 8 + g) * SX + k0];
            uint32_t b0 = *(const uint32_t*)&br[2 * t];
            uint32_t b1 = *(const uint32_t*)&br[2 * t + 8];
            mma16816(acc[nt][0], acc[nt][1], acc[nt][2], acc[nt][3],
                     a0, a1, a2, a3, b0, b1);
        }
    }

    int r0 = row0 + m0 + g, r1 = r0 + 8;
    float s0 = 1.f, s1 = 1.f;
    if (SCALE) {
        if (r0 < NN) s0 = g_ns[r0];
        if (r1 < NN) s1 = g_ns[r1];
    }
    #pragma unroll
    for (int nt = 0; nt < NT; nt++) {
        int cp = nt * 4 + t;
        if (r0 < NN)
            Yh[(size_t)r0 * YSTR + cp] = __floats2half2_rn(acc[nt][0] * s0,
                                                           acc[nt][1] * s0);
        if (r1 < NN)
            Yh[(size_t)r1 * YSTR + cp] = __floats2half2_rn(acc[nt][2] * s1,
                                                           acc[nt][3] * s1);
    }
}

// ---------------- fused: edge histogram + pack || layer-0 GEMM ----------------
__global__ void __launch_bounds__(256) histgemm0_kernel(
        const void* __restrict__ src, const void* __restrict__ dst, int E,
        int EB, const float* __restrict__ X, const float* __restrict__ W0,
        __half2* __restrict__ Yh) {
    extern __shared__ __half sh[];
    if ((int)blockIdx.x < EB) {
        __shared__ int s_is64;
        if (threadIdx.x == 0) {
            if (blockIdx.x == 0) g_epoch = g_epoch + 1;
            const long long* p = (const long long*)src;
            int n = E < 8 ? E : 8;
            int ok = 1;
            for (int j = 0; j < n; j++) {
                long long v = p[j];
                if (v < 0 || v >= (long long)NN) { ok = 0; break; }
            }
            s_is64 = ok;
        }
        __syncthreads();
        int is64 = s_is64;
        int e = blockIdx.x * 256 + threadIdx.x;
        if (e < E) {
            int s = load_idx(src, e, is64);
            int d = load_idx(dst, e, is64);
            atomicAdd(&g_cnt_out[s], 1);
            atomicAdd(&g_cnt_in [d], 1);
            g_edge[e] = make_int2(s, d);
        }
        return;
    }
    gemm_body<128, 64, 32, true, false>(X, W0, Yh, (blockIdx.x - EB) * 128, sh);
}

// ---------------- standalone GEMM (layers 1, 2) -------------------------------
template<int IN, int OUT>
__global__ void __launch_bounds__(256) gemm_mma_kernel(
        const __half* __restrict__ X, const float* __restrict__ W,
        __half2* __restrict__ Yh) {
    extern __shared__ __half sh[];
    gemm_body<IN, OUT, 32, false, true>(X, W, Yh, blockIdx.x * 128, sh);
}

// ---------------- single-launch chained scan + finalize -----------------------
__global__ void __launch_bounds__(SCAN_BS) scan_kernel(__half2* __restrict__ Yh) {
    __shared__ int sh[SCAN_BS];
    __shared__ int s_carry;
    unsigned ep = g_epoch;
    int tid = threadIdx.x, b = blockIdx.x;
    int i = b * SCAN_BS + tid;
    int v = (i < NN) ? g_cnt_in[i] : 0;
    sh[tid] = v;
    __syncthreads();
    #pragma unroll
    for (int off = 1; off < SCAN_BS; off <<= 1) {
        int t = (tid >= off) ? sh[tid - off] : 0;
        __syncthreads();
        sh[tid] += t;
        __syncthreads();
    }
    if (tid == SCAN_BS - 1)
        *(volatile unsigned long long*)&g_bsflag[b] =
            ((unsigned long long)ep << 32) | (unsigned)sh[SCAN_BS - 1];
    if (tid == 0) s_carry = 0;
    __syncthreads();
    if (tid < b) {
        volatile unsigned long long* f = &g_bsflag[tid];
        unsigned long long w;
        do { w = *f; } while ((unsigned)(w >> 32) != ep);
        atomicAdd(&s_carry, (int)(unsigned)w);
    }
    __syncthreads();
    int carry = s_carry;

    if (i < NN) {
        g_rowptr[i] = carry + sh[tid] - v;      // exclusive prefix
        int o = g_cnt_out[i];
        g_cnt_out[i] = 0;                        // pre-zero for NEXT call
        g_cnt_in [i] = 0;
        g_cursor [i] = 0;
        float nsv = (o > 0) ? rsqrtf((float)o) : 0.f;
        g_ns[i] = nsv;
        g_nd[i] = (v > 0) ? rsqrtf((float)v) : 0.f;
        __half2 h2s = __floats2half2_rn(nsv, nsv);
        __half2* yr = &Yh[(size_t)i * 32];
        #pragma unroll
        for (int j = 0; j < 32; j++)
            yr[j] = __hmul2(yr[j], h2s);
    }
    if (b == NB - 1 && tid == SCAN_BS - 1)
        g_rowptr[NN] = carry + sh[tid];          // == E
}

// ---------------- edge placement: CSR by dst, store BYTE offsets --------------
__global__ void place_kernel(int E) {
    int e = blockIdx.x * blockDim.x + threadIdx.x;
    if (e >= E) return;
    int2 sd = g_edge[e];
    int pos = g_rowptr[sd.y] + atomicAdd(&g_cursor[sd.y], 1);
    g_esrc[pos] = sd.x << 7;                     // src * 128 bytes (row stride)
}

// ---------------- fused SpMM-gather (fp16) + epilogue -------------------------
// R12 structure: 16 lanes x 4 cols (uint2), two edges per step (one per
// half-warp). esrc holds premultiplied byte offsets -> gather address is a
// single pointer+offset add (no IMAD.WIDE chain).
template<int OUT, bool RELU, bool O16>
__global__ void __launch_bounds__(256) spmm_epi_kernel(
        const __half2* __restrict__ Yh, const float* __restrict__ bias,
        void* __restrict__ OutV) {
    int row = blockIdx.x * 8 + (threadIdx.x >> 5);
    if (row >= NN) return;
    int lane = threadIdx.x & 31;
    int hi = lane >> 4, l4 = lane & 15;
    constexpr int NL = OUT / 4;              // active lanes per 16-group
    bool valid = l4 < NL;
    const char* Yb = (const char*)Yh + l4 * 8;   // lane's column base

    int beg = g_rowptr[row], end = g_rowptr[row + 1];
    float a0 = 0.f, a1 = 0.f, a2 = 0.f, a3 = 0.f;

    for (int base = beg; base < end; base += 32) {
        int rem = end - base; if (rem > 32) rem = 32;
        int my = (lane < rem) ? g_esrc[base + lane] : 0;
        int rem8 = rem & ~7;
        int j = 0;
        for (; j < rem8; j += 8) {
            #pragma unroll
            for (int u = 0; u < 4; u++) {
                int s = __shfl_sync(0xffffffffu, my, j + 2 * u + hi);
                if (valid) {
                    uint2 r = __ldg((const uint2*)(Yb + s));
                    float2 f0 = __half22float2(*(__half2*)&r.x);
                    float2 f1 = __half22float2(*(__half2*)&r.y);
                    a0 += f0.x; a1 += f0.y; a2 += f1.x; a3 += f1.y;
                }
            }
        }
        for (; j < rem; j += 2) {
            int jj = j + hi;
            int s = __shfl_sync(0xffffffffu, my, jj & 31);
            if (valid && jj < rem) {
                uint2 r = __ldg((const uint2*)(Yb + s));
                float2 f0 = __half22float2(*(__half2*)&r.x);
                float2 f1 = __half22float2(*(__half2*)&r.y);
                a0 += f0.x; a1 += f0.y; a2 += f1.x; a3 += f1.y;
            }
        }
    }
    // combine the two half-warps (each processed alternating edges)
    a0 += __shfl_xor_sync(0xffffffffu, a0, 16);
    a1 += __shfl_xor_sync(0xffffffffu, a1, 16);
    a2 += __shfl_xor_sync(0xffffffffu, a2, 16);
    a3 += __shfl_xor_sync(0xffffffffu, a3, 16);

    float ndv = g_nd[row];
    int c0 = 4 * l4;
    float v0 = -CUDART_INF_F, v1 = -CUDART_INF_F,
          v2 = -CUDART_INF_F, v3 = -CUDART_INF_F;
    if (valid) {
        float4 b = __ldg((const float4*)&bias[c0]);
        v0 = a0 * ndv + b.x; v1 = a1 * ndv + b.y;
        v2 = a2 * ndv + b.z; v3 = a3 * ndv + b.w;
        if (RELU) {
            v0 = fmaxf(v0, 0.f); v1 = fmaxf(v1, 0.f);
            v2 = fmaxf(v2, 0.f); v3 = fmaxf(v3, 0.f);
        }
    }
    // softmax reduce within each 16-lane group
    float m = fmaxf(fmaxf(v0, v1), fmaxf(v2, v3));
    #pragma unroll
    for (int o = 8; o; o >>= 1) m = fmaxf(m, __shfl_xor_sync(0xffffffffu, m, o));
    float s = valid ? (__expf(v0 - m) + __expf(v1 - m) +
                       __expf(v2 - m) + __expf(v3 - m)) : 0.f;
    #pragma unroll
    for (int o = 8; o; o >>= 1) s += __shfl_xor_sync(0xffffffffu, s, o);
    float ls = logf(s) + m;
    if (valid && hi == 0) {
        if (O16) {
            // hidden layers: dense 64-col rows == padded stride (uint2 idx 16/row)
            uint2* Out = (uint2*)OutV;
            __half2 h0 = __floats2half2_rn(v0 - ls, v1 - ls);
            __half2 h1 = __floats2half2_rn(v2 - ls, v3 - ls);
            uint2 w;
            w.x = *(uint32_t*)&h0; w.y = *(uint32_t*)&h1;
            Out[(size_t)row * 16 + l4] = w;
        } else {
            float* Out = (float*)OutV;
            *(float4*)&Out[(size_t)row * OUT + c0] =
                make_float4(v0 - ls, v1 - ls, v2 - ls, v3 - ls);
        }
    }
}

// ---------------- launcher ----------------------------------------------------
extern "C" void kernel_launch(void* const* d_in, const int* in_sizes, int n_in,
                              void* d_out, int out_size) {
    const float* feats = (const float*)d_in[0];
    const void*  src   = d_in[1];
    const void*  dst   = d_in[2];
    const float* W0    = (const float*)d_in[3];
    const float* b0    = (const float*)d_in[4];
    const float* W1    = (const float*)d_in[5];
    const float* b1    = (const float*)d_in[6];
    const float* W2    = (const float*)d_in[7];
    const float* b2    = (const float*)d_in[8];
    float* out = (float*)d_out;
    int E = in_sizes[1];

    __half2* p_y = nullptr;
    __half *p_h1 = nullptr, *p_h2 = nullptr;
    cudaGetSymbolAddress((void**)&p_y,  g_y);
    cudaGetSymbolAddress((void**)&p_h1, g_h1);
    cudaGetSymbolAddress((void**)&p_h2, g_h2);

    const int MB = (NN + 127) / 128;  // gemm blocks (128 rows each)
    const int SB = (NN + 7) / 8;      // spmm blocks (warp per row)
    const int EB = (E + 255) / 256;   // per-edge blocks

    const int sm0 = (128 * (128 + 8) + 64 * (128 + 8)) * 2;  // 52224
    const int sm1 = (128 * (64 + 8) + 64 * (64 + 8)) * 2;    // 27648
    const int sm2 = (128 * (64 + 8) + 40 * (64 + 8)) * 2;    // 24192
    cudaFuncSetAttribute(histgemm0_kernel,
                         cudaFuncAttributeMaxDynamicSharedMemorySize, sm0);

    // 1) hist+pack || GEMM0 (one launch)
    histgemm0_kernel<<<EB + MB, 256, sm0>>>(src, dst, E, EB, feats, W0, p_y);
    // 2) chained scan + finalize (+Y0*=ns, zero cnts for next call)
    scan_kernel<<<NB, SCAN_BS>>>(p_y);
    // 3) CSR placement (byte offsets)
    place_kernel<<<EB, 256>>>(E);
    // 4) layer 0 spmm+epilogue -> h1 (fp16)
    spmm_epi_kernel<64, true, true><<<SB, 256>>>(p_y, b0, p_h1);
    // 5) layer 1
    gemm_mma_kernel<64, 64><<<MB, 256, sm1>>>(p_h1, W1, p_y);
    spmm_epi_kernel<64, true, true><<<SB, 256>>>(p_y, b1, p_h2);
    // 6) layer 2 (padded Y rows, stride 128B)
    gemm_mma_kernel<64, 40><<<MB, 256, sm2>>>(p_h2, W2, p_y);
    spmm_epi_kernel<40, false, false><<<SB, 256>>>(p_y, b2, out);
}